// round 9
// baseline (speedup 1.0000x reference)
#include <cuda_runtime.h>
#include <cuda_fp16.h>
#include <math.h>
#include <stdint.h>

#define Ndim 8192
#define Fdim 128
#define Fo   64
#define Hh   4
#define NC   72          // operand cols per side: 64 feats + 1 denom + 7 pad
#define BKT  64          // k per tile
#define NTILE (Ndim / BKT)

// ---------------- scratch ----------------
__device__ __align__(16) float  g_Xp[Hh * Ndim * Fo];
__device__ __align__(16) float  g_ss[Hh * Ndim];
__device__ __align__(16) float  g_sn[Hh * Ndim];
__device__ __align__(16) __half g_snh[Hh * Ndim];   // fp16 copy of s_neigh for mask gen
__device__ __align__(16) float  g_P [Hh * Ndim];
__device__ __align__(16) float  g_Pn[Hh * Ndim];
__device__ __align__(16) float  g_Q [Hh * Ndim];
__device__ __align__(16) float  g_Qn[Hh * Ndim];
__device__ float g_mx[Hh];
// fp16 operand tables [h][side][col NC][m 8192]; side0 = Q'-scaled, side1 = Qn'-scaled
__device__ __align__(16) __half g_Y[Hh * 2 * NC * Ndim];

// ---------------- helpers ----------------
__device__ __forceinline__ uint32_t smem_u32(const void* p) {
    uint32_t a;
    asm("{ .reg .u64 t; cvta.to.shared.u64 t, %1; cvt.u32.u64 %0, t; }" : "=r"(a) : "l"(p));
    return a;
}
#define SWZ128(x) ((x) ^ (((x) >> 3) & 0x70))

__device__ __forceinline__ void ldsm4(uint32_t* r, uint32_t a) {
    asm volatile("ldmatrix.sync.aligned.m8n8.x4.shared.b16 {%0,%1,%2,%3}, [%4];"
        : "=r"(r[0]), "=r"(r[1]), "=r"(r[2]), "=r"(r[3]) : "r"(a));
}
__device__ __forceinline__ void ldsm2(uint32_t* r, uint32_t a) {
    asm volatile("ldmatrix.sync.aligned.m8n8.x2.shared.b16 {%0,%1}, [%2];"
        : "=r"(r[0]), "=r"(r[1]) : "r"(a));
}
__device__ __forceinline__ void mma16816(float* d, const uint32_t* a, const uint32_t* b) {
    asm volatile("mma.sync.aligned.m16n8k16.row.col.f32.f16.f16.f32 "
        "{%0,%1,%2,%3}, {%4,%5,%6,%7}, {%8,%9}, {%0,%1,%2,%3};"
        : "+f"(d[0]), "+f"(d[1]), "+f"(d[2]), "+f"(d[3])
        : "r"(a[0]), "r"(a[1]), "r"(a[2]), "r"(a[3]), "r"(b[0]), "r"(b[1]));
}
__device__ __forceinline__ void cp16(uint32_t smaddr, const void* gaddr) {
    asm volatile("cp.async.cg.shared.global [%0], [%1], 16;" :: "r"(smaddr), "l"(gaddr));
}
#define CP_COMMIT() asm volatile("cp.async.commit_group;" ::: "memory")
#define CP_WAIT0()  asm volatile("cp.async.wait_group 0;" ::: "memory")

// named producer/consumer barriers: count = all 384 threads
#define NTHR 384
#define BFULL0  1
#define BFULL1  2
#define BEMPTY0 3
#define BEMPTY1 4
#define BAR_SYNC(id)   asm volatile("bar.sync %0, %1;"   :: "r"(id), "n"(NTHR) : "memory")
#define BAR_ARRIVE(id) asm volatile("bar.arrive %0, %1;" :: "r"(id), "n"(NTHR) : "memory")

// ---------------- kernel 1: tiled projection Xp = X @ W[h] ----------------
__global__ __launch_bounds__(256)
void proj_kernel(const float* __restrict__ X, const float* __restrict__ W) {
    __shared__ float sX[64][65];
    __shared__ float sW[64][64];
    int t = threadIdx.x;
    int n0 = blockIdx.x * 64, h = blockIdx.y;
    int tc = t & 15, tr = t >> 4;
    float acc[4][4];
#pragma unroll
    for (int r = 0; r < 4; ++r)
#pragma unroll
        for (int c = 0; c < 4; ++c) acc[r][c] = 0.f;

    for (int k0 = 0; k0 < Fdim; k0 += 64) {
        __syncthreads();
#pragma unroll
        for (int r = 0; r < 4; ++r) {
            int idx = t + 256 * r;
            int row = idx >> 4, kq = idx & 15;
            float4 v = __ldg((const float4*)(X + (size_t)(n0 + row) * Fdim + k0) + kq);
            sX[row][kq * 4 + 0] = v.x;
            sX[row][kq * 4 + 1] = v.y;
            sX[row][kq * 4 + 2] = v.z;
            sX[row][kq * 4 + 3] = v.w;
        }
#pragma unroll
        for (int r = 0; r < 4; ++r) {
            int idx = t + 256 * r;
            int row = idx >> 4, kq = idx & 15;
            *(float4*)&sW[row][kq * 4] =
                __ldg((const float4*)(W + ((size_t)(h * Fdim) + k0 + row) * Fo) + kq);
        }
        __syncthreads();
#pragma unroll 16
        for (int kk = 0; kk < 64; ++kk) {
            float4 wv = *(const float4*)&sW[kk][tc * 4];
            float xv0 = sX[tr * 4 + 0][kk];
            float xv1 = sX[tr * 4 + 1][kk];
            float xv2 = sX[tr * 4 + 2][kk];
            float xv3 = sX[tr * 4 + 3][kk];
#define PR(r, xv) \
            acc[r][0] = fmaf(xv, wv.x, acc[r][0]); \
            acc[r][1] = fmaf(xv, wv.y, acc[r][1]); \
            acc[r][2] = fmaf(xv, wv.z, acc[r][2]); \
            acc[r][3] = fmaf(xv, wv.w, acc[r][3]);
            PR(0, xv0) PR(1, xv1) PR(2, xv2) PR(3, xv3)
#undef PR
        }
    }
#pragma unroll
    for (int r = 0; r < 4; ++r) {
        float4 o = make_float4(acc[r][0], acc[r][1], acc[r][2], acc[r][3]);
        *(float4*)(g_Xp + ((size_t)(h * Ndim + n0 + tr * 4 + r)) * Fo + tc * 4) = o;
    }
}

// ---------------- kernel 2: score halves ----------------
__global__ void score_kernel(const float* __restrict__ a_self, const float* __restrict__ a_neigh) {
    int idx = blockIdx.x * blockDim.x + threadIdx.x;   // H*N
    int h = idx >> 13;
    const float* xp = g_Xp + (size_t)idx * Fo;
    float s1 = 0.f, s2 = 0.f;
#pragma unroll 16
    for (int d = 0; d < Fo; ++d) {
        float v = xp[d];
        s1 = fmaf(v, __ldg(a_self + h * Fo + d), s1);
        s2 = fmaf(v, __ldg(a_neigh + h * Fo + d), s2);
    }
    g_ss[idx] = s1;
    g_sn[idx] = s2;
}

// ---------------- kernel 3: per-head max of s_neigh ----------------
__global__ void max_kernel() {
    __shared__ float sm[256];
    int h = blockIdx.x, t = threadIdx.x;
    float m = -1e30f;
    for (int i = t; i < Ndim; i += 256) m = fmaxf(m, g_sn[h * Ndim + i]);
    sm[t] = m;
    __syncthreads();
    for (int s = 128; s > 0; s >>= 1) {
        if (t < s) sm[t] = fmaxf(sm[t], sm[t + s]);
        __syncthreads();
    }
    if (t == 0) g_mx[h] = sm[0];
}

// ---------------- kernel 4: exp tables (range-managed for fp16) ----------------
__global__ void pq_kernel() {
    int idx = blockIdx.x * blockDim.x + threadIdx.x;   // H*N
    int h = idx >> 13;
    float ss = g_ss[idx], sn = g_sn[idx];
    float mx = g_mx[h];
    float cm = mx > 0.f ? mx : 0.2f * mx;             // lrelu(mx): Q',Qn' <= 1
    float tmx = ss + mx;
    float ci = tmx > 0.f ? tmx : 0.2f * tmx;          // row stabilizer
    g_P [idx] = expf(ss - ci);
    g_Pn[idx] = expf(0.2f * ss - ci);
    g_Q [idx] = expf(sn - cm);
    g_Qn[idx] = expf(0.2f * sn - cm);
    g_snh[idx] = __float2half_rn(sn);
}

// ---------------- kernel 5: fp16 operand tables ----------------
__global__ __launch_bounds__(256)
void y_kernel() {
    __shared__ float sXp[64][65];
    __shared__ float sQ[64], sQn[64];
    int t = threadIdx.x;
    int m0 = blockIdx.x * 64, h = blockIdx.y;

#pragma unroll
    for (int r = 0; r < 4; ++r) {
        int idx = t + 256 * r;
        int j = idx >> 4, dq = idx & 15;
        float4 v = __ldg((const float4*)(g_Xp + ((size_t)(h * Ndim + m0 + j)) * Fo) + dq);
        sXp[j][dq * 4 + 0] = v.x;
        sXp[j][dq * 4 + 1] = v.y;
        sXp[j][dq * 4 + 2] = v.z;
        sXp[j][dq * 4 + 3] = v.w;
    }
    if (t < 64) {
        sQ[t]  = g_Q [h * Ndim + m0 + t];
        sQn[t] = g_Qn[h * Ndim + m0 + t];
    }
    __syncthreads();

    for (int idx = t; idx < 2 * NC * 8; idx += 256) {   // chunks of 8 halfs
        int side = idx >= NC * 8;
        int l = side ? idx - NC * 8 : idx;
        int row = l >> 3, g8 = l & 7;
        ushort u[8];
#pragma unroll
        for (int p = 0; p < 8; ++p) {
            int m = g8 * 8 + p;
            float q = side ? sQn[m] : sQ[m];
            float v = (row < 64) ? q * sXp[m][row] : (row == 64 ? q : 0.f);
            u[p] = __half_as_ushort(__float2half_rn(v));
        }
        uint4 pk;
        pk.x = (uint32_t)u[0] | ((uint32_t)u[1] << 16);
        pk.y = (uint32_t)u[2] | ((uint32_t)u[3] << 16);
        pk.z = (uint32_t)u[4] | ((uint32_t)u[5] << 16);
        pk.w = (uint32_t)u[6] | ((uint32_t)u[7] << 16);
        *(uint4*)(g_Y + ((size_t)((h * 2 + side) * NC + row)) * Ndim + m0 + g8 * 8) = pk;
    }
}

// ---------------- main kernel: warp-specialized producer/consumer ----------------
#define HDR    4096
#define S_B    0
#define S_C    16384
#define S_YB   32768
#define S_YC   41984
#define STAGE  51200
#define SMEM_DYN (1024 + HDR + 2 * STAGE)
#define NCP    76

__global__ __launch_bounds__(NTHR, 1)
void gat_mma(const float* __restrict__ A, float* __restrict__ out) {
    extern __shared__ char dsm[];
    uint32_t sb0 = smem_u32(dsm);
    uint32_t sb = (sb0 + 1023u) & ~1023u;
    char* smp = dsm + (sb - sb0);

    int t = threadIdx.x, wid = t >> 5, lane = t & 31;
    int h = blockIdx.y, n0 = blockIdx.x * 128;

    float* sP   = (float*)(smp + 512);
    float* sPn  = (float*)(smp + 1024);
    float* sInv = (float*)(smp + 1536);
    if (t < 128) {
        int g = h * Ndim + n0 + t;
        sP[t]  = g_P[g];
        sPn[t] = g_Pn[g];
    }

    float acc[2][9][4];   // consumer accumulators (unused by producers)

    if (wid < 8) {
        // ================= CONSUMERS (warps 0..7) =================
        int side = wid >> 2;          // 0: B-side (P), 1: C-side (Pn)
        int rg   = wid & 3;
        int row0 = rg * 32;
        int la15 = lane & 15, la7 = lane & 7;
        uint32_t aRow  = (uint32_t)(row0 + la15) * 128 + ((lane >> 4) ? 16u : 0u);
        uint32_t bRow  = (uint32_t)la7 * 128 + (((lane >> 3) & 1) ? 16u : 0u);
        uint32_t bRow4 = bRow + (uint32_t)(lane >> 4) * 1024;

#pragma unroll
        for (int rt = 0; rt < 2; ++rt)
#pragma unroll
            for (int nt = 0; nt < 9; ++nt)
#pragma unroll
                for (int c = 0; c < 4; ++c) acc[rt][nt][c] = 0.f;

        BAR_ARRIVE(BEMPTY0);     // both buffers start empty
        BAR_ARRIVE(BEMPTY1);

        for (int tile = 0; tile < NTILE; ++tile) {
            int buf = tile & 1;
            uint32_t stc = HDR + (uint32_t)buf * STAGE;
            BAR_SYNC(BFULL0 + buf);

            uint32_t mbase = sb + stc + (side ? S_C : S_B);
            uint32_t ybase = sb + stc + (side ? S_YC : S_YB);
#pragma unroll
            for (int ks = 0; ks < 4; ++ks) {
                uint32_t a0[4], a1[4];
                ldsm4(a0, mbase + SWZ128(aRow + ks * 32));
                ldsm4(a1, mbase + SWZ128(aRow + 2048 + ks * 32));
#pragma unroll
                for (int np = 0; np < 4; ++np) {
                    uint32_t b4[4];
                    ldsm4(b4, ybase + SWZ128(bRow4 + (uint32_t)np * 2048 + ks * 32));
                    mma16816(acc[0][np * 2 + 0], a0, b4);
                    mma16816(acc[1][np * 2 + 0], a1, b4);
                    mma16816(acc[0][np * 2 + 1], a0, b4 + 2);
                    mma16816(acc[1][np * 2 + 1], a1, b4 + 2);
                }
                {
                    uint32_t b[2];
                    ldsm2(b, ybase + SWZ128(bRow + 8u * 1024 + ks * 32));
                    mma16816(acc[0][8], a0, b);
                    mma16816(acc[1][8], a1, b);
                }
            }
            BAR_ARRIVE(BEMPTY0 + buf);
        }
    } else {
        // ================= PRODUCERS (warps 8..11) =================
        int p  = t - 256;             // 0..127
        int q  = p & 15;              // float4 col within k-tile
        int i0 = p >> 4;              // rows i0 + 8r, r < 16
        __half2 pssh[16];
#pragma unroll
        for (int r = 0; r < 16; ++r)
            pssh[r] = __float2half2_rn(g_ss[h * Ndim + n0 + i0 + 8 * r]);
        const __half2 hz = __float2half2_rn(0.f);
        const float4* A4 = (const float4*)A;

        for (int tile = 0; tile < NTILE; ++tile) {
            int buf = tile & 1;
            uint32_t st = HDR + (uint32_t)buf * STAGE;
            int m0 = tile * BKT;
            BAR_SYNC(BEMPTY0 + buf);

            // Y operands via cp.async
            for (int idx = p; idx < 2 * NC * 8; idx += 128) {
                int sd = idx >= NC * 8;
                int l = sd ? idx - NC * 8 : idx;
                int row = l >> 3, kq = l & 7;
                const __half* gp = g_Y + ((size_t)((h * 2 + sd) * NC + row)) * Ndim + m0 + kq * 8;
                cp16(sb + st + (sd ? S_YC : S_YB) + SWZ128((uint32_t)(row * 128 + kq * 16)), gp);
            }
            CP_COMMIT();

            uint2 snp = *(const uint2*)(g_snh + h * Ndim + m0 + q * 4);
            __half2 sn01 = *(__half2*)&snp.x, sn23 = *(__half2*)&snp.y;
#pragma unroll
            for (int hb = 0; hb < 2; ++hb) {     // 2 batches of 8 rows (bounds registers)
                float4 av[8];
#pragma unroll
                for (int r = 0; r < 8; ++r)
                    av[r] = __ldg(A4 + (size_t)(n0 + i0 + 8 * (hb * 8 + r)) * (Ndim / 4) + (m0 >> 2) + q);
#pragma unroll
                for (int r = 0; r < 8; ++r) {
                    int rr = hb * 8 + r;
                    int i = i0 + 8 * rr;
                    __half2 a01 = __floats2half2_rn(av[r].x, av[r].y);
                    __half2 a23 = __floats2half2_rn(av[r].z, av[r].w);
                    __half2 b01 = __hmul2(a01, __hgt2(__hadd2(pssh[rr], sn01), hz));
                    __half2 b23 = __hmul2(a23, __hgt2(__hadd2(pssh[rr], sn23), hz));
                    __half2 c01 = __hsub2(a01, b01);
                    __half2 c23 = __hsub2(a23, b23);
                    uint32_t off = SWZ128((uint32_t)(i * 128 + q * 8));
                    *(uint2*)(smp + st + S_B + off) = make_uint2(*(uint32_t*)&b01, *(uint32_t*)&b23);
                    *(uint2*)(smp + st + S_C + off) = make_uint2(*(uint32_t*)&c01, *(uint32_t*)&c23);
                }
            }
            CP_WAIT0();
            asm volatile("membar.cta;" ::: "memory");
            BAR_ARRIVE(BFULL0 + buf);
        }
    }

    __syncthreads();   // all 384: everyone done with stage buffers

    // ---- epilogue ----
    if (wid < 8) {
        int side = wid >> 2;
        int row0 = (wid & 3) * 32;
        float* sc = (float*)(smp + HDR + (side ? 40960 : 0));
#pragma unroll
        for (int rt = 0; rt < 2; ++rt)
#pragma unroll
            for (int nt = 0; nt < 9; ++nt) {
                int row = row0 + rt * 16 + (lane >> 2);
                int col = nt * 8 + (lane & 3) * 2;
                *(float2*)&sc[row * NCP + col]       = make_float2(acc[rt][nt][0], acc[rt][nt][1]);
                *(float2*)&sc[(row + 8) * NCP + col] = make_float2(acc[rt][nt][2], acc[rt][nt][3]);
            }
    }
    __syncthreads();

    float* scB = (float*)(smp + HDR);
    float* scC = (float*)(smp + HDR + 40960);
    if (t < 128) {
        float den = sP[t] * scB[t * NCP + 64] + sPn[t] * scC[t * NCP + 64];
        sInv[t] = 1.0f / den;
    }
    __syncthreads();

    for (int idx = t; idx < 128 * 64; idx += NTHR) {
        int row = idx >> 6, col = idx & 63;
        float v = (sP[row] * scB[row * NCP + col] + sPn[row] * scC[row * NCP + col]) * sInv[row];
        out[(size_t)(n0 + row) * (Hh * Fo) + h * Fo + col] = fmaxf(v, 0.f);
    }
}

// ---------------- launcher ----------------
extern "C" void kernel_launch(void* const* d_in, const int* in_sizes, int n_in,
                              void* d_out, int out_size) {
    const float* X       = (const float*)d_in[0];
    const float* A       = (const float*)d_in[1];
    const float* W       = (const float*)d_in[2];
    const float* a_self  = (const float*)d_in[3];
    const float* a_neigh = (const float*)d_in[4];
    float* out = (float*)d_out;

    cudaFuncSetAttribute(gat_mma, cudaFuncAttributeMaxDynamicSharedMemorySize, SMEM_DYN);

    proj_kernel <<<dim3(Ndim / 64, Hh), 256>>>(X, W);
    score_kernel<<<(Hh * Ndim) / 256, 256>>>(a_self, a_neigh);
    max_kernel  <<<Hh, 256>>>();
    pq_kernel   <<<(Hh * Ndim) / 256, 256>>>();
    y_kernel    <<<dim3(Ndim / 64, Hh), 256>>>();

    gat_mma<<<dim3(Ndim / 128, Hh), NTHR, SMEM_DYN>>>(A, out);
}

// round 10
// speedup vs baseline: 1.7475x; 1.7475x over previous
#include <cuda_runtime.h>
#include <cuda_fp16.h>
#include <math.h>
#include <stdint.h>

#define Ndim 8192
#define Fdim 128
#define Fo   64
#define Hh   4
#define NC   72          // operand cols: 64 feats + 1 ones(denom) + 7 pad
#define BKT  64          // k per tile
#define NTILE (Ndim / BKT)

// ---------------- scratch ----------------
__device__ __align__(16) float  g_Xp[Hh * Ndim * Fo];
__device__ __align__(16) float  g_ss[Hh * Ndim];
__device__ __align__(16) float  g_sn[Hh * Ndim];
__device__ __align__(16) __half g_snh[Hh * Ndim];   // fp16 s_neigh for mask test
__device__ __align__(16) float  g_P [Hh * Ndim];
__device__ __align__(16) float  g_Pn[Hh * Ndim];
__device__ __align__(16) __half g_qh [Hh * Ndim];   // fp16 exp(sn - cm)
__device__ __align__(16) __half g_qnh[Hh * Ndim];   // fp16 exp(0.2 sn - cm)
__device__ float g_mx[Hh];
// fp16 plain-Xp operand table [h][col NC][m]
__device__ __align__(16) __half g_Yp[Hh * NC * Ndim];

// ---------------- helpers ----------------
__device__ __forceinline__ uint32_t smem_u32(const void* p) {
    uint32_t a;
    asm("{ .reg .u64 t; cvta.to.shared.u64 t, %1; cvt.u32.u64 %0, t; }" : "=r"(a) : "l"(p));
    return a;
}
#define SWZ128(x) ((x) ^ (((x) >> 3) & 0x70))

__device__ __forceinline__ void ldsm4(uint32_t* r, uint32_t a) {
    asm volatile("ldmatrix.sync.aligned.m8n8.x4.shared.b16 {%0,%1,%2,%3}, [%4];"
        : "=r"(r[0]), "=r"(r[1]), "=r"(r[2]), "=r"(r[3]) : "r"(a));
}
__device__ __forceinline__ void ldsm2(uint32_t* r, uint32_t a) {
    asm volatile("ldmatrix.sync.aligned.m8n8.x2.shared.b16 {%0,%1}, [%2];"
        : "=r"(r[0]), "=r"(r[1]) : "r"(a));
}
__device__ __forceinline__ void mma16816(float* d, const uint32_t* a, const uint32_t* b) {
    asm volatile("mma.sync.aligned.m16n8k16.row.col.f32.f16.f16.f32 "
        "{%0,%1,%2,%3}, {%4,%5,%6,%7}, {%8,%9}, {%0,%1,%2,%3};"
        : "+f"(d[0]), "+f"(d[1]), "+f"(d[2]), "+f"(d[3])
        : "r"(a[0]), "r"(a[1]), "r"(a[2]), "r"(a[3]), "r"(b[0]), "r"(b[1]));
}
__device__ __forceinline__ void cp16(uint32_t smaddr, const void* gaddr) {
    asm volatile("cp.async.cg.shared.global [%0], [%1], 16;" :: "r"(smaddr), "l"(gaddr));
}
#define CP_COMMIT() asm volatile("cp.async.commit_group;" ::: "memory")
#define CP_WAIT0()  asm volatile("cp.async.wait_group 0;" ::: "memory")

// ---------------- kernel 1: tiled projection Xp = X @ W[h] ----------------
__global__ __launch_bounds__(256)
void proj_kernel(const float* __restrict__ X, const float* __restrict__ W) {
    __shared__ float sX[64][65];
    __shared__ float sW[64][64];
    int t = threadIdx.x;
    int n0 = blockIdx.x * 64, h = blockIdx.y;
    int tc = t & 15, tr = t >> 4;
    float acc[4][4];
#pragma unroll
    for (int r = 0; r < 4; ++r)
#pragma unroll
        for (int c = 0; c < 4; ++c) acc[r][c] = 0.f;

    for (int k0 = 0; k0 < Fdim; k0 += 64) {
        __syncthreads();
#pragma unroll
        for (int r = 0; r < 4; ++r) {
            int idx = t + 256 * r;
            int row = idx >> 4, kq = idx & 15;
            float4 v = __ldg((const float4*)(X + (size_t)(n0 + row) * Fdim + k0) + kq);
            sX[row][kq * 4 + 0] = v.x;
            sX[row][kq * 4 + 1] = v.y;
            sX[row][kq * 4 + 2] = v.z;
            sX[row][kq * 4 + 3] = v.w;
        }
#pragma unroll
        for (int r = 0; r < 4; ++r) {
            int idx = t + 256 * r;
            int row = idx >> 4, kq = idx & 15;
            *(float4*)&sW[row][kq * 4] =
                __ldg((const float4*)(W + ((size_t)(h * Fdim) + k0 + row) * Fo) + kq);
        }
        __syncthreads();
#pragma unroll 16
        for (int kk = 0; kk < 64; ++kk) {
            float4 wv = *(const float4*)&sW[kk][tc * 4];
            float xv0 = sX[tr * 4 + 0][kk];
            float xv1 = sX[tr * 4 + 1][kk];
            float xv2 = sX[tr * 4 + 2][kk];
            float xv3 = sX[tr * 4 + 3][kk];
#define PR(r, xv) \
            acc[r][0] = fmaf(xv, wv.x, acc[r][0]); \
            acc[r][1] = fmaf(xv, wv.y, acc[r][1]); \
            acc[r][2] = fmaf(xv, wv.z, acc[r][2]); \
            acc[r][3] = fmaf(xv, wv.w, acc[r][3]);
            PR(0, xv0) PR(1, xv1) PR(2, xv2) PR(3, xv3)
#undef PR
        }
    }
#pragma unroll
    for (int r = 0; r < 4; ++r) {
        float4 o = make_float4(acc[r][0], acc[r][1], acc[r][2], acc[r][3]);
        *(float4*)(g_Xp + ((size_t)(h * Ndim + n0 + tr * 4 + r)) * Fo + tc * 4) = o;
    }
}

// ---------------- kernel 2: score halves ----------------
__global__ void score_kernel(const float* __restrict__ a_self, const float* __restrict__ a_neigh) {
    int idx = blockIdx.x * blockDim.x + threadIdx.x;   // H*N
    int h = idx >> 13;
    const float* xp = g_Xp + (size_t)idx * Fo;
    float s1 = 0.f, s2 = 0.f;
#pragma unroll 16
    for (int d = 0; d < Fo; ++d) {
        float v = xp[d];
        s1 = fmaf(v, __ldg(a_self + h * Fo + d), s1);
        s2 = fmaf(v, __ldg(a_neigh + h * Fo + d), s2);
    }
    g_ss[idx] = s1;
    g_sn[idx] = s2;
}

// ---------------- kernel 3: per-head max of s_neigh ----------------
__global__ void max_kernel() {
    __shared__ float sm[256];
    int h = blockIdx.x, t = threadIdx.x;
    float m = -1e30f;
    for (int i = t; i < Ndim; i += 256) m = fmaxf(m, g_sn[h * Ndim + i]);
    sm[t] = m;
    __syncthreads();
    for (int s = 128; s > 0; s >>= 1) {
        if (t < s) sm[t] = fmaxf(sm[t], sm[t + s]);
        __syncthreads();
    }
    if (t == 0) g_mx[h] = sm[0];
}

// ---------------- kernel 4: exp tables (range-managed for fp16) ----------------
__global__ void pq_kernel() {
    int idx = blockIdx.x * blockDim.x + threadIdx.x;   // H*N
    int h = idx >> 13;
    float ss = g_ss[idx], sn = g_sn[idx];
    float mx = g_mx[h];
    float cm = mx > 0.f ? mx : 0.2f * mx;             // lrelu(mx): Q,Qn <= ~1
    float tmx = ss + mx;
    float ci = tmx > 0.f ? tmx : 0.2f * tmx;          // row stabilizer
    g_P [idx] = expf(ss - ci);
    g_Pn[idx] = expf(0.2f * ss - ci);
    g_qh [idx] = __float2half_rn(expf(sn - cm));
    g_qnh[idx] = __float2half_rn(expf(0.2f * sn - cm));
    g_snh[idx] = __float2half_rn(sn);
}

// ---------------- kernel 5: fp16 plain-Xp operand table ----------------
__global__ __launch_bounds__(256)
void y_kernel() {
    __shared__ float sXp[64][65];
    int t = threadIdx.x;
    int m0 = blockIdx.x * 64, h = blockIdx.y;

#pragma unroll
    for (int r = 0; r < 4; ++r) {
        int idx = t + 256 * r;
        int j = idx >> 4, dq = idx & 15;
        float4 v = __ldg((const float4*)(g_Xp + ((size_t)(h * Ndim + m0 + j)) * Fo) + dq);
        sXp[j][dq * 4 + 0] = v.x;
        sXp[j][dq * 4 + 1] = v.y;
        sXp[j][dq * 4 + 2] = v.z;
        sXp[j][dq * 4 + 3] = v.w;
    }
    __syncthreads();

    for (int idx = t; idx < NC * 8; idx += 256) {   // chunks of 8 halfs
        int row = idx >> 3, g8 = idx & 7;
        ushort u[8];
#pragma unroll
        for (int p = 0; p < 8; ++p) {
            int m = g8 * 8 + p;
            float v = (row < 64) ? sXp[m][row] : (row == 64 ? 1.f : 0.f);
            u[p] = __half_as_ushort(__float2half_rn(v));
        }
        uint4 pk;
        pk.x = (uint32_t)u[0] | ((uint32_t)u[1] << 16);
        pk.y = (uint32_t)u[2] | ((uint32_t)u[3] << 16);
        pk.z = (uint32_t)u[4] | ((uint32_t)u[5] << 16);
        pk.w = (uint32_t)u[6] | ((uint32_t)u[7] << 16);
        *(uint4*)(g_Yp + ((size_t)(h * NC + row)) * Ndim + m0 + g8 * 8) = pk;
    }
}

// ---------------- main kernel: single fused-weight fp16 HMMA GEMM ----------------
// smem (1024-aligned base): stage[buf] @ buf*25600: S_W=0 (16KB), S_Y=16384 (9216B)
#define S_W    0
#define S_Y    16384
#define STAGE  25600
#define SMEM_DYN (1024 + 2 * STAGE)

__global__ __launch_bounds__(256, 2)
void gat_mma(const float* __restrict__ A, float* __restrict__ out) {
    extern __shared__ char dsm[];
    uint32_t sb0 = smem_u32(dsm);
    uint32_t sb = (sb0 + 1023u) & ~1023u;
    char* smp = dsm + (sb - sb0);

    int t = threadIdx.x, wid = t >> 5, lane = t & 31;
    int h = blockIdx.y, n0 = blockIdx.x * 128;

    // weight-gen thread mapping: q = float4 col in k-tile, rows i0 + 16r
    int q  = t & 15;
    int i0 = t >> 4;
    __half2 ssh[8], Ph[8], Pnh[8];
#pragma unroll
    for (int r = 0; r < 8; ++r) {
        int gi = h * Ndim + n0 + i0 + 16 * r;
        ssh[r] = __float2half2_rn(g_ss[gi]);
        Ph[r]  = __float2half2_rn(g_P[gi]);
        Pnh[r] = __float2half2_rn(g_Pn[gi]);
    }
    const __half2 hz = __float2half2_rn(0.f);
    const float4* A4 = (const float4*)A;
    const __half* snh = g_snh + h * Ndim;
    const __half* qh  = g_qh  + h * Ndim;
    const __half* qnh = g_qnh + h * Ndim;

    // mma addressing: warp owns rows wid*16..wid*16+15, all 9 n-tiles
    uint32_t aRow  = (uint32_t)(wid * 16 + (lane & 15)) * 128 + ((lane >> 4) ? 16u : 0u);
    uint32_t bRow  = (uint32_t)(lane & 7) * 128 + (((lane >> 3) & 1) ? 16u : 0u);
    uint32_t bRow4 = bRow + (uint32_t)(lane >> 4) * 1024;

    float acc[9][4];
#pragma unroll
    for (int nt = 0; nt < 9; ++nt)
#pragma unroll
        for (int c = 0; c < 4; ++c) acc[nt][c] = 0.f;

    // ---- prologue: stage 0 ----
    {
        for (int idx = t; idx < NC * 8; idx += 256) {
            int row = idx >> 3, kq = idx & 7;
            cp16(sb + S_Y + SWZ128((uint32_t)(row * 128 + kq * 16)),
                 g_Yp + ((size_t)(h * NC + row)) * Ndim + kq * 8);
        }
        CP_COMMIT();
        uint2 snp = *(const uint2*)(snh + q * 4);
        uint2 qp  = *(const uint2*)(qh  + q * 4);
        uint2 qnp = *(const uint2*)(qnh + q * 4);
        __half2 sn01 = *(__half2*)&snp.x, sn23 = *(__half2*)&snp.y;
        __half2 q01  = *(__half2*)&qp.x,  q23  = *(__half2*)&qp.y;
        __half2 qn01 = *(__half2*)&qnp.x, qn23 = *(__half2*)&qnp.y;
        float4 av[8];
#pragma unroll
        for (int r = 0; r < 8; ++r)
            av[r] = __ldg(A4 + (size_t)(n0 + i0 + 16 * r) * (Ndim / 4) + q);
#pragma unroll
        for (int r = 0; r < 8; ++r) {
            int i = i0 + 16 * r;
            __half2 a01 = __floats2half2_rn(av[r].x, av[r].y);
            __half2 a23 = __floats2half2_rn(av[r].z, av[r].w);
            __half2 g01 = __hgt2(__hadd2(ssh[r], sn01), hz);
            __half2 g23 = __hgt2(__hadd2(ssh[r], sn23), hz);
            __half2 pq01 = __hmul2(Ph[r], q01),  pn01 = __hmul2(Pnh[r], qn01);
            __half2 pq23 = __hmul2(Ph[r], q23),  pn23 = __hmul2(Pnh[r], qn23);
            __half2 w01 = __hmul2(a01, __hfma2(g01, __hsub2(pq01, pn01), pn01));
            __half2 w23 = __hmul2(a23, __hfma2(g23, __hsub2(pq23, pn23), pn23));
            uint32_t off = SWZ128((uint32_t)(i * 128 + q * 8));
            *(uint2*)(smp + S_W + off) = make_uint2(*(uint32_t*)&w01, *(uint32_t*)&w23);
        }
        CP_WAIT0();
        __syncthreads();
    }

    // ---- main loop ----
    for (int tile = 0; tile < NTILE; ++tile) {
        int cur = tile & 1;
        uint32_t stc = (uint32_t)cur * STAGE;
        uint32_t stn = (uint32_t)(cur ^ 1) * STAGE;
        int m1 = (tile + 1) * BKT;

        float4 av[8];
        __half2 sn01, sn23, q01, q23, qn01, qn23;
        if (tile < NTILE - 1) {
            for (int idx = t; idx < NC * 8; idx += 256) {
                int row = idx >> 3, kq = idx & 7;
                cp16(sb + stn + S_Y + SWZ128((uint32_t)(row * 128 + kq * 16)),
                     g_Yp + ((size_t)(h * NC + row)) * Ndim + m1 + kq * 8);
            }
            CP_COMMIT();
            uint2 snp = *(const uint2*)(snh + m1 + q * 4);
            uint2 qp  = *(const uint2*)(qh  + m1 + q * 4);
            uint2 qnp = *(const uint2*)(qnh + m1 + q * 4);
            sn01 = *(__half2*)&snp.x; sn23 = *(__half2*)&snp.y;
            q01  = *(__half2*)&qp.x;  q23  = *(__half2*)&qp.y;
            qn01 = *(__half2*)&qnp.x; qn23 = *(__half2*)&qnp.y;
#pragma unroll
            for (int r = 0; r < 8; ++r)
                av[r] = __ldg(A4 + (size_t)(n0 + i0 + 16 * r) * (Ndim / 4) + (m1 >> 2) + q);
        }

        // ---- mma on current stage ----
        uint32_t wbase = sb + stc + S_W;
        uint32_t ybase = sb + stc + S_Y;
#pragma unroll
        for (int ks = 0; ks < 4; ++ks) {
            uint32_t a4[4];
            ldsm4(a4, wbase + SWZ128(aRow + ks * 32));
#pragma unroll
            for (int np = 0; np < 4; ++np) {
                uint32_t b4[4];
                ldsm4(b4, ybase + SWZ128(bRow4 + (uint32_t)np * 2048 + ks * 32));
                mma16816(acc[np * 2 + 0], a4, b4);
                mma16816(acc[np * 2 + 1], a4, b4 + 2);
            }
            {
                uint32_t b2[2];
                ldsm2(b2, ybase + SWZ128(bRow + 8192u + ks * 32));
                mma16816(acc[8], a4, b2);
            }
        }

        // ---- generate next W tile ----
        if (tile < NTILE - 1) {
#pragma unroll
            for (int r = 0; r < 8; ++r) {
                int i = i0 + 16 * r;
                __half2 a01 = __floats2half2_rn(av[r].x, av[r].y);
                __half2 a23 = __floats2half2_rn(av[r].z, av[r].w);
                __half2 g01 = __hgt2(__hadd2(ssh[r], sn01), hz);
                __half2 g23 = __hgt2(__hadd2(ssh[r], sn23), hz);
                __half2 pq01 = __hmul2(Ph[r], q01),  pn01 = __hmul2(Pnh[r], qn01);
                __half2 pq23 = __hmul2(Ph[r], q23),  pn23 = __hmul2(Pnh[r], qn23);
                __half2 w01 = __hmul2(a01, __hfma2(g01, __hsub2(pq01, pn01), pn01));
                __half2 w23 = __hmul2(a23, __hfma2(g23, __hsub2(pq23, pn23), pn23));
                uint32_t off = SWZ128((uint32_t)(i * 128 + q * 8));
                *(uint2*)(smp + stn + S_W + off) = make_uint2(*(uint32_t*)&w01, *(uint32_t*)&w23);
            }
            CP_WAIT0();
        }
        __syncthreads();
    }

    // ---- register epilogue: den from col 64 (ones column), shuffle-broadcast ----
    float den0 = __shfl_sync(0xffffffffu, acc[8][0], lane & 28);
    float den1 = __shfl_sync(0xffffffffu, acc[8][2], lane & 28);
    float inv0 = 1.0f / den0;
    float inv1 = 1.0f / den1;
    int rowg = n0 + wid * 16 + (lane >> 2);
    float* op0 = out + (size_t)rowg * (Hh * Fo) + h * Fo;
    float* op1 = op0 + (size_t)8 * (Hh * Fo);
#pragma unroll
    for (int nt = 0; nt < 8; ++nt) {
        int c = nt * 8 + (lane & 3) * 2;
        float2 v0 = make_float2(fmaxf(acc[nt][0] * inv0, 0.f), fmaxf(acc[nt][1] * inv0, 0.f));
        float2 v1 = make_float2(fmaxf(acc[nt][2] * inv1, 0.f), fmaxf(acc[nt][3] * inv1, 0.f));
        *(float2*)(op0 + c) = v0;
        *(float2*)(op1 + c) = v1;
    }
}

// ---------------- launcher ----------------
extern "C" void kernel_launch(void* const* d_in, const int* in_sizes, int n_in,
                              void* d_out, int out_size) {
    const float* X       = (const float*)d_in[0];
    const float* A       = (const float*)d_in[1];
    const float* W       = (const float*)d_in[2];
    const float* a_self  = (const float*)d_in[3];
    const float* a_neigh = (const float*)d_in[4];
    float* out = (float*)d_out;

    cudaFuncSetAttribute(gat_mma, cudaFuncAttributeMaxDynamicSharedMemorySize, SMEM_DYN);

    proj_kernel <<<dim3(Ndim / 64, Hh), 256>>>(X, W);
    score_kernel<<<(Hh * Ndim) / 256, 256>>>(a_self, a_neigh);
    max_kernel  <<<Hh, 256>>>();
    pq_kernel   <<<(Hh * Ndim) / 256, 256>>>();
    y_kernel    <<<dim3(Ndim / 64, Hh), 256>>>();

    gat_mma<<<dim3(Ndim / 128, Hh), 256, SMEM_DYN>>>(A, out);
}